// round 14
// baseline (speedup 1.0000x reference)
#include <cuda_runtime.h>
#include <cstdint>

typedef unsigned long long ull;

// ---- f32x2 packed helpers (sm_100+ PTX) ------------------------------------

__device__ __forceinline__ ull pack2(float lo, float hi) {
    ull r;
    asm("mov.b64 %0, {%1, %2};" : "=l"(r) : "f"(lo), "f"(hi));
    return r;
}

__device__ __forceinline__ ull midpair(ull a, ull b) {
    ull r;
    asm("{\n\t"
        ".reg .b32 alo, ahi, blo, bhi;\n\t"
        "mov.b64 {alo, ahi}, %1;\n\t"
        "mov.b64 {blo, bhi}, %2;\n\t"
        "mov.b64 %0, {ahi, blo};\n\t"
        "}"
        : "=l"(r) : "l"(a), "l"(b));
    return r;
}

__device__ __forceinline__ void fma2(ull& d, ull a, ull b) {
    asm("fma.rn.f32x2 %0, %1, %2, %0;" : "+l"(d) : "l"(a), "l"(b));
}

// ---- kernel -----------------------------------------------------------------

#define C_CH   64
#define H_IN   512
#define W_IN   512
#define H_OUT  510
#define W_OUT  510
#define TY     10                 // output rows per tile
#define ROWS   (TY + 2)           // input rows per tile (12)
#define NT     17                 // tiles per strip (3 strips * 17 * 10 = 510)
#define STRIPY (NT * TY)          // 170 output rows per strip
#define NTHR   256
#define CHUNKS (ROWS * W_IN * 4 / 16)   // 1536 x 16B per tile

// issue one tile's loads into smem buffer (fire-and-forget)
__device__ __forceinline__ void issue_tile(uint32_t sdst, const char* gsrc) {
#pragma unroll
    for (int i = 0; i < CHUNKS / NTHR; ++i) {          // 6 chunks/thread
        const int k = i * NTHR + threadIdx.x;
        asm volatile("cp.async.cg.shared.global [%0], [%1], 16;"
                     :: "r"(sdst + k * 16), "l"(gsrc + (size_t)k * 16));
    }
    asm volatile("cp.async.commit_group;");
}

__global__ void __launch_bounds__(NTHR, 4)
dwconv3x3_dbuf_kernel(const float* __restrict__ x,
                      const float* __restrict__ w,
                      float* __restrict__ out)
{
    __shared__ float s[2][ROWS * W_IN];   // 2 x 24576 B

    const int tid   = threadIdx.x;
    const int strip = blockIdx.x;         // 0..2
    const int plane = blockIdx.y;         // 0..1023
    const int c     = plane & (C_CH - 1);

    const float* ip = x + (size_t)plane * (H_IN * W_IN)
                        + (size_t)(strip * STRIPY) * W_IN;
    float*       op = out + (size_t)plane * (H_OUT * W_OUT)
                          + (size_t)(strip * STRIPY) * W_OUT + 2 * tid;

    uint32_t sb0;
    asm("{ .reg .u64 t; cvta.to.shared.u64 t, %1; cvt.u32.u64 %0, t; }"
        : "=r"(sb0) : "l"(&s[0][0]));
    const uint32_t sbuf[2] = { sb0, sb0 + ROWS * W_IN * 4 };

    // prefetch tile 0
    issue_tile(sbuf[0], reinterpret_cast<const char*>(ip));

    // weights (overlap with cp.async)
    const float* wp = w + c * 9;
    ull wv[9];
#pragma unroll
    for (int i = 0; i < 9; ++i) {
        const float wf = __ldg(wp + i);
        wv[i] = pack2(wf, wf);
    }

    for (int t = 0; t < NT; ++t) {
        if (t + 1 < NT) {
            issue_tile(sbuf[(t + 1) & 1],
                       reinterpret_cast<const char*>(ip + (size_t)(t + 1) * TY * W_IN));
            asm volatile("cp.async.wait_group 1;");   // tile t ready
        } else {
            asm volatile("cp.async.wait_group 0;");
        }
        __syncthreads();

        if (tid < W_OUT / 2) {                        // 255 compute threads
            const float* sb = s[t & 1];
            ull acc[TY];
#pragma unroll
            for (int o = 0; o < TY; ++o) acc[o] = 0ull;

#pragma unroll
            for (int r = 0; r < ROWS; ++r) {
                const float* srow = sb + r * W_IN + 2 * tid;
                const ull A = *reinterpret_cast<const ull*>(srow);
                const ull B = *reinterpret_cast<const ull*>(srow + 2);
                const ull M = midpair(A, B);

#pragma unroll
                for (int ky = 0; ky < 3; ++ky) {
                    const int o = r - ky;
                    if (o >= 0 && o < TY) {
                        fma2(acc[o], wv[ky * 3 + 0], A);
                        fma2(acc[o], wv[ky * 3 + 1], M);
                        fma2(acc[o], wv[ky * 3 + 2], B);
                    }
                }
            }

            float* orow = op + (size_t)t * TY * W_OUT;
#pragma unroll
            for (int o = 0; o < TY; ++o)
                *reinterpret_cast<ull*>(orow + (size_t)o * W_OUT) = acc[o];
        }
        __syncthreads();   // compute(t) done before buffer t&1 is refilled at t+2
    }
}

// ---- launch -----------------------------------------------------------------

extern "C" void kernel_launch(void* const* d_in, const int* in_sizes, int n_in,
                              void* d_out, int out_size)
{
    const float* x   = (const float*)d_in[0];   // (16, 64, 512, 512) fp32
    const float* w   = (const float*)d_in[1];   // (64, 3, 3) fp32
    float*       out = (float*)d_out;           // (16, 64, 510, 510) fp32

    dim3 grid(H_OUT / STRIPY, 16 * C_CH);       // (3, 1024)
    dim3 block(NTHR);
    dwconv3x3_dbuf_kernel<<<grid, block>>>(x, w, out);
}

// round 16
// speedup vs baseline: 1.0598x; 1.0598x over previous
#include <cuda_runtime.h>
#include <cstdint>

typedef unsigned long long ull;

// ---- f32x2 packed helpers (sm_100+ PTX) ------------------------------------

__device__ __forceinline__ ull pack2(float lo, float hi) {
    ull r;
    asm("mov.b64 %0, {%1, %2};" : "=l"(r) : "f"(lo), "f"(hi));
    return r;
}

// {a.hi, b.lo} — middle pair, register re-pairing only
__device__ __forceinline__ ull midpair(ull a, ull b) {
    ull r;
    asm("{\n\t"
        ".reg .b32 alo, ahi, blo, bhi;\n\t"
        "mov.b64 {alo, ahi}, %1;\n\t"
        "mov.b64 {blo, bhi}, %2;\n\t"
        "mov.b64 %0, {ahi, blo};\n\t"
        "}"
        : "=l"(r) : "l"(a), "l"(b));
    return r;
}

// d += a * b on packed f32x2
__device__ __forceinline__ void fma2(ull& d, ull a, ull b) {
    asm("fma.rn.f32x2 %0, %1, %2, %0;" : "+l"(d) : "l"(a), "l"(b));
}

// ---- kernel -----------------------------------------------------------------

#define C_CH   64
#define H_IN   512
#define W_IN   512
#define H_OUT  510
#define W_OUT  510
#define TY     15                 // output rows per CTA tile (510 = 34*15)
#define ROWS   (TY + 2)           // input rows staged in smem (17)
#define NTHR   256
#define CHUNKS (ROWS * W_IN * 4 / 16)   // 2176 x 16B

__global__ void __launch_bounds__(NTHR, 5)
dwconv3x3_cpa15_kernel(const float* __restrict__ x,
                       const float* __restrict__ w,
                       float* __restrict__ out)
{
    __shared__ float s[ROWS * W_IN];   // 17*512*4 = 34816 B

    const int tid   = threadIdx.x;
    const int ytile = blockIdx.x;      // 0..33
    const int plane = blockIdx.y;      // n*C + c, 0..1023
    const int c     = plane & (C_CH - 1);
    const int iy0   = ytile * TY;      // first input row of tile

    // ---- cooperative coalesced tile load via cp.async (no dest registers) ----
    {
        const char* gbase = reinterpret_cast<const char*>(
            x + (size_t)plane * (H_IN * W_IN) + (size_t)iy0 * W_IN);
        uint32_t sbase;
        asm("{ .reg .u64 t; cvta.to.shared.u64 t, %1; cvt.u32.u64 %0, t; }"
            : "=r"(sbase) : "l"(s));
#pragma unroll
        for (int k = tid; k < CHUNKS; k += NTHR) {    // 8-9 chunks/thread
            asm volatile("cp.async.cg.shared.global [%0], [%1], 16;"
                         :: "r"(sbase + k * 16), "l"(gbase + (size_t)k * 16));
        }
        asm volatile("cp.async.commit_group;");
    }

    // ---- weights: splat 9 taps into packed f32x2 (overlaps with cp.async) ----
    const float* wp = w + c * 9;
    ull wv[9];
#pragma unroll
    for (int i = 0; i < 9; ++i) {
        const float wf = __ldg(wp + i);
        wv[i] = pack2(wf, wf);
    }

    asm volatile("cp.async.wait_group 0;");
    __syncthreads();

    // ---- compute: thread t owns output x-pair (2t, 2t+1), rows 0..TY-1 ----
    if (tid < W_OUT / 2) {             // 255 compute threads, 1 idle
        ull acc[TY];
#pragma unroll
        for (int o = 0; o < TY; ++o) acc[o] = 0ull;

#pragma unroll
        for (int r = 0; r < ROWS; ++r) {
            const float* srow = s + r * W_IN + 2 * tid;
            const ull A = *reinterpret_cast<const ull*>(srow);      // (i0,i1)
            const ull B = *reinterpret_cast<const ull*>(srow + 2);  // (i2,i3)
            const ull M = midpair(A, B);                            // (i1,i2)

#pragma unroll
            for (int ky = 0; ky < 3; ++ky) {
                const int o = r - ky;
                if (o >= 0 && o < TY) {
                    fma2(acc[o], wv[ky * 3 + 0], A);
                    fma2(acc[o], wv[ky * 3 + 1], M);
                    fma2(acc[o], wv[ky * 3 + 2], B);
                }
            }
        }

        float* op = out + (size_t)plane * (H_OUT * W_OUT)
                        + (size_t)iy0 * W_OUT + 2 * tid;
#pragma unroll
        for (int o = 0; o < TY; ++o)
            *reinterpret_cast<ull*>(op + (size_t)o * W_OUT) = acc[o];
    }
}

// ---- launch -----------------------------------------------------------------

extern "C" void kernel_launch(void* const* d_in, const int* in_sizes, int n_in,
                              void* d_out, int out_size)
{
    const float* x   = (const float*)d_in[0];   // (16, 64, 512, 512) fp32
    const float* w   = (const float*)d_in[1];   // (64, 3, 3) fp32
    float*       out = (float*)d_out;           // (16, 64, 510, 510) fp32

    dim3 grid(H_OUT / TY, 16 * C_CH);           // (34, 1024)
    dim3 block(NTHR);
    dwconv3x3_cpa15_kernel<<<grid, block>>>(x, w, out);
}